// round 1
// baseline (speedup 1.0000x reference)
#include <cuda_runtime.h>

#define RES      256
#define NTRI     1000
#define NBATCH   2
#define EPSF     1e-8f
#define PFLOATS  12            // A0 B0 C0 A1 B1 C1 A2 B2 C2 mn inv pad

// scratch: per (batch, triangle) parameter block
__device__ float g_params[NBATCH * NTRI * PFLOATS];

// ---------------------------------------------------------------------------
// Kernel 1: projection + edge-coefficient setup. grid = (NBATCH), 256 threads.
// term_i(px,py) = N*(e_i.x*(v_i.y - py) - e_i.y*(v_i.x - px))
//              = [N*(e_i.x*v_i.y - e_i.y*v_i.x)] + [N*e_i.y]*px + [-N*e_i.x]*py
// ---------------------------------------------------------------------------
__global__ void setup_kernel(const float* __restrict__ meshes,
                             const float* __restrict__ K,
                             const int*   __restrict__ model_idxs,
                             const float* __restrict__ poses)
{
    const int b = blockIdx.x;
    __shared__ float M[12];                       // M = K @ cam (3x4)
    if (threadIdx.x < 12) {
        int r = threadIdx.x / 4, c = threadIdx.x % 4;
        float s = 0.0f;
        #pragma unroll
        for (int k = 0; k < 3; k++)
            s += K[r * 3 + k] * poses[b * 12 + k * 4 + c];
        M[threadIdx.x] = s;
    }
    __syncthreads();

    const int mi = model_idxs[b];
    const float* __restrict__ mesh = meshes + (size_t)mi * NTRI * 9;

    for (int t = threadIdx.x; t < NTRI; t += blockDim.x) {
        float vx[3], vy[3];
        #pragma unroll
        for (int j = 0; j < 3; j++) {
            float X = mesh[t * 9 + j * 3 + 0];
            float Y = mesh[t * 9 + j * 3 + 1];
            float Z = mesh[t * 9 + j * 3 + 2];
            float x = M[0] * X + M[1] * Y + M[2]  * Z + M[3];
            float y = M[4] * X + M[5] * Y + M[6]  * Z + M[7];
            float w = M[8] * X + M[9] * Y + M[10] * Z + M[11];
            float iw = 1.0f / (w + EPSF);
            vx[j] = x * iw;
            vy[j] = y * iw;
        }
        float e0x = vx[1] - vx[0], e0y = vy[1] - vy[0];
        float e1x = vx[2] - vx[1], e1y = vy[2] - vy[1];
        float e2x = vx[0] - vx[2], e2y = vy[0] - vy[2];
        float N = e0x * e2y - e0y * e2x + EPSF;

        float* P = g_params + (size_t)(b * NTRI + t) * PFLOATS;
        P[0] = N * (e0x * vy[0] - e0y * vx[0]);  P[1] =  N * e0y;  P[2] = -N * e0x;
        P[3] = N * (e1x * vy[1] - e1y * vx[1]);  P[4] =  N * e1y;  P[5] = -N * e1x;
        P[6] = N * (e2x * vy[2] - e2y * vx[2]);  P[7] =  N * e2y;  P[8] = -N * e2x;
        P[9] = 0.0f; P[10] = 0.0f; P[11] = 0.0f;
    }
}

// ---------------------------------------------------------------------------
// Kernel 2: per-triangle min/max of score over all 65536 pixels.
// grid = (NTRI, NBATCH), 256 threads; thread tid owns px = tid, loops py.
// Scoring formula ordering IDENTICAL to kernel 3 so score >= mn holds exactly.
// ---------------------------------------------------------------------------
__global__ void minmax_kernel()
{
    const int b = blockIdx.y;
    const int t = blockIdx.x;
    float* P = g_params + (size_t)(b * NTRI + t) * PFLOATS;

    const float A0 = P[0], B0 = P[1], C0 = P[2];
    const float A1 = P[3], B1 = P[4], C1 = P[5];
    const float A2 = P[6], B2 = P[7], C2 = P[8];

    const float px = (float)threadIdx.x;
    const float p0 = fmaf(B0, px, A0);
    const float p1 = fmaf(B1, px, A1);
    const float p2 = fmaf(B2, px, A2);

    float mn =  INFINITY;
    float mx = -INFINITY;
    #pragma unroll 4
    for (int py = 0; py < RES; py++) {
        float fpy = (float)py;
        float t0 = fmaxf(fmaf(C0, fpy, p0), 0.0f);
        float t1 = fmaxf(fmaf(C1, fpy, p1), 0.0f);
        float t2 = fmaxf(fmaf(C2, fpy, p2), 0.0f);
        float s = t0 * t1 * t2;
        mn = fminf(mn, s);
        mx = fmaxf(mx, s);
    }

    // block reduction (256 threads = 8 warps)
    #pragma unroll
    for (int o = 16; o > 0; o >>= 1) {
        mn = fminf(mn, __shfl_xor_sync(0xffffffffu, mn, o));
        mx = fmaxf(mx, __shfl_xor_sync(0xffffffffu, mx, o));
    }
    __shared__ float smn[8], smx[8];
    int w = threadIdx.x >> 5, l = threadIdx.x & 31;
    if (l == 0) { smn[w] = mn; smx[w] = mx; }
    __syncthreads();
    if (threadIdx.x == 0) {
        float rmn = smn[0], rmx = smx[0];
        #pragma unroll
        for (int i = 1; i < 8; i++) {
            rmn = fminf(rmn, smn[i]);
            rmx = fmaxf(rmx, smx[i]);
        }
        P[9]  = rmn;
        P[10] = 1.0f / (rmx - rmn + EPSF);
    }
}

// ---------------------------------------------------------------------------
// Kernel 3: per-pixel accumulation over all triangles.
// grid = (P/256, NBATCH), 256 threads, 1 pixel per thread.
// Triangle params staged in shared (48 KB), read as 3x float4 per triangle.
// Contribution is tanh((score-mn)*inv); skipped exactly when score == mn.
// ---------------------------------------------------------------------------
__global__ void raster_kernel(float* __restrict__ out)
{
    __shared__ float sh[NTRI * PFLOATS];          // 48000 B
    const int b = blockIdx.y;
    const float* __restrict__ gp = g_params + (size_t)b * NTRI * PFLOATS;

    for (int i = threadIdx.x; i < NTRI * PFLOATS; i += blockDim.x)
        sh[i] = gp[i];
    __syncthreads();

    const int p  = blockIdx.x * blockDim.x + threadIdx.x;   // 0..65535
    const float px = (float)(p >> 8);
    const float py = (float)(p & 255);

    float acc = 0.0f;
    const float4* __restrict__ q = (const float4*)sh;

    for (int t = 0; t < NTRI; t++) {
        float4 q0 = q[t * 3 + 0];   // A0 B0 C0 A1
        float4 q1 = q[t * 3 + 1];   // B1 C1 A2 B2
        float4 q2 = q[t * 3 + 2];   // C2 mn inv pad

        float t0 = fmaxf(fmaf(q0.z, py, fmaf(q0.y, px, q0.x)), 0.0f);
        float t1 = fmaxf(fmaf(q1.y, py, fmaf(q1.x, px, q0.w)), 0.0f);
        float t2 = fmaxf(fmaf(q2.x, py, fmaf(q1.w, px, q1.z)), 0.0f);
        float s  = t0 * t1 * t2;
        float d  = s - q2.y;
        if (d > 0.0f)
            acc += tanhf(d * q2.z);
    }

    out[(size_t)b * (RES * RES) + p] = acc;
}

// ---------------------------------------------------------------------------
extern "C" void kernel_launch(void* const* d_in, const int* in_sizes, int n_in,
                              void* d_out, int out_size)
{
    const float* meshes = (const float*)d_in[0];
    const float* K      = (const float*)d_in[1];
    const int*   idxs   = (const int*)  d_in[2];
    const float* poses  = (const float*)d_in[3];
    float*       out    = (float*)d_out;

    setup_kernel<<<NBATCH, 256>>>(meshes, K, idxs, poses);

    dim3 g1(NTRI, NBATCH);
    minmax_kernel<<<g1, 256>>>();

    dim3 g2((RES * RES) / 256, NBATCH);
    raster_kernel<<<g2, 256>>>(out);
}